// round 7
// baseline (speedup 1.0000x reference)
#include <cuda_runtime.h>
#include <math.h>

#define BATCH  2
#define NTOK   962
#define DIM    384
#define NH     6
#define DH     64
#define NLAYER 12
#define ROWS   (BATCH*NTOK)          // 1924
#define QKVD   (3*DIM)               // 1152
#define HIDD   (4*DIM)               // 1536
#define FEAT_SIZE (ROWS*DIM)         // 738816
#define ATTN_SIZE (BATCH*NH*NTOK*NTOK)

// ---------------- scratch (static device globals; no allocation) -------------
__device__ float g_x  [ROWS*DIM];
__device__ float g_ln [ROWS*DIM];
__device__ float g_qkv[ROWS*QKVD];
__device__ float g_attn[ATTN_SIZE];     // 44.4 MB scores/probs
__device__ float g_ctx[ROWS*DIM];
__device__ float g_hid[ROWS*HIDD];

// ---------------- generic tiled SGEMM ---------------------------------------
// C[M,N] = act( alpha * A[M,K] @ B(K,N) + bias ) + res
//   TRANSB=false: B stored row-major [K,N], ldb = row stride
//   TRANSB=true : B stored row-major [N,K], ldb = row stride (computes A@B^T)
// Batched over blockIdx.z with z = zb*Hn + zh and independent strides.
#define TBM 64
#define TBN 64
#define TBK 16

template<bool TRANSB, bool DOGELU>
__global__ __launch_bounds__(256) void gemm_k(
    const float* __restrict__ A, const float* __restrict__ B,
    const float* __restrict__ bias, const float* __restrict__ res,
    float* __restrict__ C,
    int M, int N, int K, int lda, int ldb, int ldc, int Hn,
    long long sAb, long long sAh, long long sBb, long long sBh,
    long long sCb, long long sCh, float alpha)
{
    __shared__ float As[TBK][TBM + 4];
    __shared__ float Bs[TBK][TBN + 4];

    const int zb = blockIdx.z / Hn;
    const int zh = blockIdx.z % Hn;
    A += zb * sAb + zh * sAh;
    B += zb * sBb + zh * sBh;
    C += zb * sCb + zh * sCh;

    const int t  = threadIdx.x;
    const int tx = t & 15;
    const int ty = t >> 4;
    const int row0 = blockIdx.y * TBM;
    const int col0 = blockIdx.x * TBN;

    float acc[4][4] = {};

    for (int k0 = 0; k0 < K; k0 += TBK) {
        // ---- load A tile (64x16): idx -> m = idx/16, k = idx%16 (coalesced in k)
        #pragma unroll
        for (int i = 0; i < 4; i++) {
            int idx = t + i * 256;
            int m = idx >> 4, k = idx & 15;
            int gm = row0 + m, gk = k0 + k;
            As[k][m] = (gm < M && gk < K) ? A[(long long)gm * lda + gk] : 0.f;
        }
        // ---- load B tile (16x64)
        #pragma unroll
        for (int i = 0; i < 4; i++) {
            int idx = t + i * 256;
            if (TRANSB) {
                int n = idx >> 4, k = idx & 15;
                int gn = col0 + n, gk = k0 + k;
                Bs[k][n] = (gn < N && gk < K) ? B[(long long)gn * ldb + gk] : 0.f;
            } else {
                int k = idx >> 6, n = idx & 63;
                int gk = k0 + k, gn = col0 + n;
                Bs[k][n] = (gk < K && gn < N) ? B[(long long)gk * ldb + gn] : 0.f;
            }
        }
        __syncthreads();

        #pragma unroll
        for (int kk = 0; kk < TBK; kk++) {
            float a0 = As[kk][ty*4+0], a1 = As[kk][ty*4+1];
            float a2 = As[kk][ty*4+2], a3 = As[kk][ty*4+3];
            float b0 = Bs[kk][tx*4+0], b1 = Bs[kk][tx*4+1];
            float b2 = Bs[kk][tx*4+2], b3 = Bs[kk][tx*4+3];
            acc[0][0] += a0*b0; acc[0][1] += a0*b1; acc[0][2] += a0*b2; acc[0][3] += a0*b3;
            acc[1][0] += a1*b0; acc[1][1] += a1*b1; acc[1][2] += a1*b2; acc[1][3] += a1*b3;
            acc[2][0] += a2*b0; acc[2][1] += a2*b1; acc[2][2] += a2*b2; acc[2][3] += a2*b3;
            acc[3][0] += a3*b0; acc[3][1] += a3*b1; acc[3][2] += a3*b2; acc[3][3] += a3*b3;
        }
        __syncthreads();
    }

    #pragma unroll
    for (int i = 0; i < 4; i++) {
        int gm = row0 + ty * 4 + i;
        if (gm >= M) continue;
        #pragma unroll
        for (int j = 0; j < 4; j++) {
            int gn = col0 + tx * 4 + j;
            if (gn >= N) continue;
            float v = acc[i][j] * alpha;
            if (bias) v += bias[gn];
            if (DOGELU) v = 0.5f * v * (1.f + erff(v * 0.70710678118654752440f));
            if (res) v += res[(long long)gm * ldc + gn];
            C[(long long)gm * ldc + gn] = v;
        }
    }
}

// ---------------- layernorm: one block per row, D=384 ------------------------
__global__ __launch_bounds__(128) void ln_k(
    const float* __restrict__ x, const float* __restrict__ g,
    const float* __restrict__ b, float* __restrict__ o)
{
    __shared__ float sh[4];
    long long row = blockIdx.x;
    const float* xr = x + row * DIM;
    float* orow = o + row * DIM;
    int t = threadIdx.x;

    float v0 = xr[t], v1 = xr[t + 128], v2 = xr[t + 256];
    float s = v0 + v1 + v2;
    #pragma unroll
    for (int ofs = 16; ofs; ofs >>= 1) s += __shfl_xor_sync(0xffffffffu, s, ofs);
    if ((t & 31) == 0) sh[t >> 5] = s;
    __syncthreads();
    float mean = (sh[0] + sh[1] + sh[2] + sh[3]) * (1.f / DIM);
    __syncthreads();

    float d0 = v0 - mean, d1 = v1 - mean, d2 = v2 - mean;
    float q = d0*d0 + d1*d1 + d2*d2;
    #pragma unroll
    for (int ofs = 16; ofs; ofs >>= 1) q += __shfl_xor_sync(0xffffffffu, q, ofs);
    if ((t & 31) == 0) sh[t >> 5] = q;
    __syncthreads();
    float var = (sh[0] + sh[1] + sh[2] + sh[3]) * (1.f / DIM);
    float r = rsqrtf(var + 1e-6f);

    orow[t]       = d0 * r * g[t]       + b[t];
    orow[t + 128] = d1 * r * g[t + 128] + b[t + 128];
    orow[t + 256] = d2 * r * g[t + 256] + b[t + 256];
}

// ---------------- softmax + threshold mask + renormalize (one block/row) -----
// Reference: p = softmax(s); keep p >= 0.1*max(p); p /= sum(kept).
// max(p) = exp(0)/sum = 1/sum exactly (exp(0)==1.0f), so thresh = 0.1f*(1/sum).
__global__ __launch_bounds__(256) void softmax_k(
    const float* __restrict__ S, float* __restrict__ P)
{
    __shared__ float sh[8];
    long long row = blockIdx.x;
    const float* sr = S + row * NTOK;
    float* pr = P + row * NTOK;
    int t = threadIdx.x;

    float v[4];
    float mx = -3.4e38f;
    #pragma unroll
    for (int i = 0; i < 4; i++) {
        int j = t + i * 256;
        v[i] = (j < NTOK) ? sr[j] : -3.4e38f;
        mx = fmaxf(mx, v[i]);
    }
    #pragma unroll
    for (int ofs = 16; ofs; ofs >>= 1) mx = fmaxf(mx, __shfl_xor_sync(0xffffffffu, mx, ofs));
    if ((t & 31) == 0) sh[t >> 5] = mx;
    __syncthreads();
    float smax = sh[0];
    #pragma unroll
    for (int i = 1; i < 8; i++) smax = fmaxf(smax, sh[i]);
    __syncthreads();

    float sum = 0.f;
    #pragma unroll
    for (int i = 0; i < 4; i++) {
        float e = expf(v[i] - smax);   // OOB lanes: exp(-huge)=0
        v[i] = e;
        sum += e;
    }
    #pragma unroll
    for (int ofs = 16; ofs; ofs >>= 1) sum += __shfl_xor_sync(0xffffffffu, sum, ofs);
    if ((t & 31) == 0) sh[t >> 5] = sum;
    __syncthreads();
    float S1 = sh[0] + sh[1] + sh[2] + sh[3] + sh[4] + sh[5] + sh[6] + sh[7];
    __syncthreads();

    float thresh = 0.1f * (1.0f / S1);
    float sum2 = 0.f;
    #pragma unroll
    for (int i = 0; i < 4; i++) {
        float p = v[i] / S1;
        v[i] = (p >= thresh) ? p : 0.f;
        sum2 += v[i];
    }
    #pragma unroll
    for (int ofs = 16; ofs; ofs >>= 1) sum2 += __shfl_xor_sync(0xffffffffu, sum2, ofs);
    if ((t & 31) == 0) sh[t >> 5] = sum2;
    __syncthreads();
    float S2 = sh[0] + sh[1] + sh[2] + sh[3] + sh[4] + sh[5] + sh[6] + sh[7];

    #pragma unroll
    for (int i = 0; i < 4; i++) {
        int j = t + i * 256;
        if (j < NTOK) pr[j] = v[i] / S2;
    }
}

__global__ void copy_k(const float* __restrict__ a, float* __restrict__ o, int n)
{
    int i = blockIdx.x * 256 + threadIdx.x;
    if (i < n) o[i] = a[i];
}

// -----------------------------------------------------------------------------
extern "C" void kernel_launch(void* const* d_in, const int* in_sizes, int n_in,
                              void* d_out, int out_size)
{
    const float* x_in   = (const float*)d_in[0];
    const float* w_qkv  = (const float*)d_in[1];
    const float* b_qkv  = (const float*)d_in[2];
    const float* w_proj = (const float*)d_in[3];
    const float* b_proj = (const float*)d_in[4];
    const float* ln1g   = (const float*)d_in[5];
    const float* ln1b   = (const float*)d_in[6];
    const float* ln2g   = (const float*)d_in[7];
    const float* ln2b   = (const float*)d_in[8];
    const float* w_fc1  = (const float*)d_in[9];
    const float* b_fc1  = (const float*)d_in[10];
    const float* w_fc2  = (const float*)d_in[11];
    const float* b_fc2  = (const float*)d_in[12];
    const float* lnfg   = (const float*)d_in[13];
    const float* lnfb   = (const float*)d_in[14];

    float* out_feat = (float*)d_out;
    float* out_attn = out_feat + FEAT_SIZE;

    float *x_, *ln_, *qkv_, *attn_, *ctx_, *hid_;
    cudaGetSymbolAddress((void**)&x_,   g_x);
    cudaGetSymbolAddress((void**)&ln_,  g_ln);
    cudaGetSymbolAddress((void**)&qkv_, g_qkv);
    cudaGetSymbolAddress((void**)&attn_, g_attn);
    cudaGetSymbolAddress((void**)&ctx_, g_ctx);
    cudaGetSymbolAddress((void**)&hid_, g_hid);

    copy_k<<<(FEAT_SIZE + 255) / 256, 256>>>(x_in, x_, FEAT_SIZE);

    const int mBlk = (ROWS + TBM - 1) / TBM;          // 31
    const int sBlk = (NTOK + TBM - 1) / TBM;          // 16

    for (int l = 0; l < NLAYER; l++) {
        // LN1
        ln_k<<<ROWS, 128>>>(x_, ln1g + l * DIM, ln1b + l * DIM, ln_);

        // QKV = ln1 @ w_qkv[l] + b_qkv[l]    [1924 x 1152]
        gemm_k<false, false><<<dim3(QKVD / TBN, mBlk, 1), 256>>>(
            ln_, w_qkv + (long long)l * DIM * QKVD, b_qkv + l * QKVD, nullptr, qkv_,
            ROWS, QKVD, DIM, DIM, QKVD, QKVD, 1, 0, 0, 0, 0, 0, 0, 1.f);

        // scores[b,h] = Q @ K^T * dh^-0.5   (12 batches of 962x962x64)
        gemm_k<true, false><<<dim3(sBlk, sBlk, BATCH * NH), 256>>>(
            qkv_ /*Q*/, qkv_ + DIM /*K*/, nullptr, nullptr, attn_,
            NTOK, NTOK, DH, QKVD, QKVD, NTOK, NH,
            (long long)NTOK * QKVD, DH,
            (long long)NTOK * QKVD, DH,
            (long long)NH * NTOK * NTOK, (long long)NTOK * NTOK, 0.125f);

        // softmax + mask + renorm (last layer writes straight into d_out attn region)
        float* pdst = (l == NLAYER - 1) ? out_attn : attn_;
        softmax_k<<<BATCH * NH * NTOK, 256>>>(attn_, pdst);

        // ctx[b,n,h*64+d] = P @ V
        gemm_k<false, false><<<dim3(1, sBlk, BATCH * NH), 256>>>(
            pdst, qkv_ + 2 * DIM /*V*/, nullptr, nullptr, ctx_,
            NTOK, DH, NTOK, NTOK, QKVD, DIM, NH,
            (long long)NH * NTOK * NTOK, (long long)NTOK * NTOK,
            (long long)NTOK * QKVD, DH,
            (long long)NTOK * DIM, DH, 1.f);

        // x += ctx @ w_proj[l] + b_proj[l]
        gemm_k<false, false><<<dim3(DIM / TBN, mBlk, 1), 256>>>(
            ctx_, w_proj + (long long)l * DIM * DIM, b_proj + l * DIM, x_, x_,
            ROWS, DIM, DIM, DIM, DIM, DIM, 1, 0, 0, 0, 0, 0, 0, 1.f);

        // LN2
        ln_k<<<ROWS, 128>>>(x_, ln2g + l * DIM, ln2b + l * DIM, ln_);

        // hid = gelu(ln2 @ w_fc1[l] + b_fc1[l])   [1924 x 1536]
        gemm_k<false, true><<<dim3(HIDD / TBN, mBlk, 1), 256>>>(
            ln_, w_fc1 + (long long)l * DIM * HIDD, b_fc1 + l * HIDD, nullptr, hid_,
            ROWS, HIDD, DIM, DIM, HIDD, HIDD, 1, 0, 0, 0, 0, 0, 0, 1.f);

        // x += hid @ w_fc2[l] + b_fc2[l]
        gemm_k<false, false><<<dim3(DIM / TBN, mBlk, 1), 256>>>(
            hid_, w_fc2 + (long long)l * HIDD * DIM, b_fc2 + l * DIM, x_, x_,
            ROWS, DIM, HIDD, HIDD, DIM, DIM, 1, 0, 0, 0, 0, 0, 0, 1.f);
    }

    // final LN -> feats
    ln_k<<<ROWS, 128>>>(x_, lnfg, lnfb, out_feat);
}